// round 1
// baseline (speedup 1.0000x reference)
#include <cuda_runtime.h>
#include <cuda_bf16.h>

// Gumbel-softmax palette quantization, fused single pass.
// probs = softmax((images + gumbel)/T, axis=k);  out = einsum('bhwk,bkc->bhwc', probs, palettes)
// gumbel = -log(-log(u+EPS)+EPS)
// Single pass: exp((x+g)/T) never overflows fp32 here (<=~1e22), so no max-subtraction needed.
// out_c = (sum_k p_k * pal_kc) / (sum_k p_k)

#define KDIM 256
#define CDIM 4
#define EPSF 1e-20f

__device__ __forceinline__ float gexp(float x, float u, float invT) {
    // w = -log(u+eps)+eps ; p = exp((x - log(w)) * invT)
    float w = EPSF - __logf(u + EPSF);
    return __expf((x - __logf(w)) * invT);
}

__global__ __launch_bounds__(256)
void gsq_kernel(const float* __restrict__ images,
                const float* __restrict__ palettes,
                const float* __restrict__ noise,
                const float* __restrict__ temp,
                float* __restrict__ out,
                int hw)
{
    const int lane = threadIdx.x & 31;
    const int wid  = threadIdx.x >> 5;
    const int batch = blockIdx.y;
    const int warps_per_block = blockDim.x >> 5;
    const int warp_global = blockIdx.x * warps_per_block + wid;
    const int warp_stride = gridDim.x * warps_per_block;

    const float invT = __fdividef(1.0f, temp[0]);

    // Palette entries for this lane's 8 k-indices, kept in registers.
    // Lane's k set: {4*lane+j, j<4} and {128+4*lane+j, j<4}, matching the
    // float4 image load pattern below.
    const float4* __restrict__ pal =
        (const float4*)(palettes + (size_t)batch * KDIM * CDIM);
    float4 P0[4], P1[4];
#pragma unroll
    for (int j = 0; j < 4; ++j) {
        P0[j] = pal[4 * lane + j];
        P1[j] = pal[128 + 4 * lane + j];
    }

    const size_t base_b = (size_t)batch * hw * KDIM;

    for (int p = warp_global; p < hw; p += warp_stride) {
        const float4* __restrict__ img =
            (const float4*)(images + base_b + (size_t)p * KDIM);
        const float4* __restrict__ nse =
            (const float4*)(noise + base_b + (size_t)p * KDIM);

        // 4 independent 512B-coalesced loads -> good MLP
        float4 a0 = img[lane];
        float4 a1 = img[32 + lane];
        float4 n0 = nse[lane];
        float4 n1 = nse[32 + lane];

        float s = 0.0f;
        float accx = 0.0f, accy = 0.0f, accz = 0.0f, accw = 0.0f;

        float pe;
        pe = gexp(a0.x, n0.x, invT); s += pe;
        accx = fmaf(pe, P0[0].x, accx); accy = fmaf(pe, P0[0].y, accy);
        accz = fmaf(pe, P0[0].z, accz); accw = fmaf(pe, P0[0].w, accw);

        pe = gexp(a0.y, n0.y, invT); s += pe;
        accx = fmaf(pe, P0[1].x, accx); accy = fmaf(pe, P0[1].y, accy);
        accz = fmaf(pe, P0[1].z, accz); accw = fmaf(pe, P0[1].w, accw);

        pe = gexp(a0.z, n0.z, invT); s += pe;
        accx = fmaf(pe, P0[2].x, accx); accy = fmaf(pe, P0[2].y, accy);
        accz = fmaf(pe, P0[2].z, accz); accw = fmaf(pe, P0[2].w, accw);

        pe = gexp(a0.w, n0.w, invT); s += pe;
        accx = fmaf(pe, P0[3].x, accx); accy = fmaf(pe, P0[3].y, accy);
        accz = fmaf(pe, P0[3].z, accz); accw = fmaf(pe, P0[3].w, accw);

        pe = gexp(a1.x, n1.x, invT); s += pe;
        accx = fmaf(pe, P1[0].x, accx); accy = fmaf(pe, P1[0].y, accy);
        accz = fmaf(pe, P1[0].z, accz); accw = fmaf(pe, P1[0].w, accw);

        pe = gexp(a1.y, n1.y, invT); s += pe;
        accx = fmaf(pe, P1[1].x, accx); accy = fmaf(pe, P1[1].y, accy);
        accz = fmaf(pe, P1[1].z, accz); accw = fmaf(pe, P1[1].w, accw);

        pe = gexp(a1.z, n1.z, invT); s += pe;
        accx = fmaf(pe, P1[2].x, accx); accy = fmaf(pe, P1[2].y, accy);
        accz = fmaf(pe, P1[2].z, accz); accw = fmaf(pe, P1[2].w, accw);

        pe = gexp(a1.w, n1.w, invT); s += pe;
        accx = fmaf(pe, P1[3].x, accx); accy = fmaf(pe, P1[3].y, accy);
        accz = fmaf(pe, P1[3].z, accz); accw = fmaf(pe, P1[3].w, accw);

        // 5-value butterfly reduction across the warp
#pragma unroll
        for (int off = 16; off > 0; off >>= 1) {
            s    += __shfl_xor_sync(0xffffffffu, s,    off);
            accx += __shfl_xor_sync(0xffffffffu, accx, off);
            accy += __shfl_xor_sync(0xffffffffu, accy, off);
            accz += __shfl_xor_sync(0xffffffffu, accz, off);
            accw += __shfl_xor_sync(0xffffffffu, accw, off);
        }

        if (lane == 0) {
            float inv = __fdividef(1.0f, s);
            float4 o;
            o.x = accx * inv; o.y = accy * inv; o.z = accz * inv; o.w = accw * inv;
            ((float4*)out)[(size_t)batch * hw + p] = o;
        }
    }
}

extern "C" void kernel_launch(void* const* d_in, const int* in_sizes, int n_in,
                              void* d_out, int out_size) {
    const float* images   = (const float*)d_in[0];
    const float* palettes = (const float*)d_in[1];
    const float* noise    = (const float*)d_in[2];
    const float* temp     = (const float*)d_in[3];
    float* out = (float*)d_out;

    int batches = in_sizes[1] / (KDIM * CDIM);               // 8
    int hw = (int)(in_sizes[0] / ((size_t)batches * KDIM));  // 65536

    dim3 block(256, 1, 1);
    dim3 grid(256, batches, 1); // 256 blocks/batch x 8 warps -> 32 pixels per warp
    gsq_kernel<<<grid, block>>>(images, palettes, noise, temp, out, hw);
}

// round 2
// speedup vs baseline: 1.0237x; 1.0237x over previous
#include <cuda_runtime.h>
#include <cuda_bf16.h>

// Gumbel-softmax palette quantization, fused single pass.
// probs = softmax((images + gumbel)/T, axis=k);  out = einsum('bhwk,bkc->bhwc', probs, palettes)
// gumbel = -log(-log(u+EPS)+EPS)
// Single pass (no max-subtract): exp((x+g)/T) <= ~1e22 here, far from fp32 overflow.
// out_c = (sum_k p_k * pal_kc) / (sum_k p_k)
//
// R2: palette moved regs -> smem (conflict-free permuted layout), freeing ~32 regs;
//     __launch_bounds__(256,6) forces 48 warps/SM for DRAM latency hiding;
//     __ldcs streaming loads for the read-once image/noise tensors.

#define KDIM 256
#define CDIM 4
#define EPSF 1e-20f

__device__ __forceinline__ float gexp(float x, float u, float invT) {
    // w = -log(u+eps)+eps ; p = exp((x - log(w)) * invT)
    float w = EPSF - __logf(u + EPSF);
    return __expf((x - __logf(w)) * invT);
}

__global__ __launch_bounds__(256, 6)
void gsq_kernel(const float* __restrict__ images,
                const float* __restrict__ palettes,
                const float* __restrict__ noise,
                const float* __restrict__ temp,
                float* __restrict__ out,
                int hw)
{
    __shared__ float4 spal[256];   // 4KB, permuted: spal[j*32+lane] = pal[4*lane+j] (lo half), +128 for hi

    const int lane = threadIdx.x & 31;
    const int wid  = threadIdx.x >> 5;
    const int batch = blockIdx.y;
    const int warps_per_block = blockDim.x >> 5;
    const int warp_global = blockIdx.x * warps_per_block + wid;
    const int warp_stride = gridDim.x * warps_per_block;

    const float invT = __fdividef(1.0f, temp[0]);

    // Fill smem palette, permuted so that lane's LDS address stride is 16B
    // (consecutive lanes -> consecutive float4) => conflict-free LDS.128.
    {
        const float4* __restrict__ pal =
            (const float4*)(palettes + (size_t)batch * KDIM * CDIM);
        int e = threadIdx.x;                     // palette entry index 0..255
        int el = e & 127;                        // index within half
        int dst = (e & 128) + ((el & 3) << 5) + (el >> 2);
        spal[dst] = pal[e];
    }
    __syncthreads();

    const size_t base_b = (size_t)batch * hw * KDIM;

    for (int p = warp_global; p < hw; p += warp_stride) {
        const float4* __restrict__ img =
            (const float4*)(images + base_b + (size_t)p * KDIM);
        const float4* __restrict__ nse =
            (const float4*)(noise + base_b + (size_t)p * KDIM);

        // 4 independent 512B-coalesced streaming loads -> good MLP, no cache pollution
        float4 a0 = __ldcs(img + lane);
        float4 a1 = __ldcs(img + 32 + lane);
        float4 n0 = __ldcs(nse + lane);
        float4 n1 = __ldcs(nse + 32 + lane);

        float s = 0.0f;
        float accx = 0.0f, accy = 0.0f, accz = 0.0f, accw = 0.0f;

        float pe; float4 P;

        pe = gexp(a0.x, n0.x, invT); s += pe; P = spal[lane];
        accx = fmaf(pe, P.x, accx); accy = fmaf(pe, P.y, accy);
        accz = fmaf(pe, P.z, accz); accw = fmaf(pe, P.w, accw);

        pe = gexp(a0.y, n0.y, invT); s += pe; P = spal[32 + lane];
        accx = fmaf(pe, P.x, accx); accy = fmaf(pe, P.y, accy);
        accz = fmaf(pe, P.z, accz); accw = fmaf(pe, P.w, accw);

        pe = gexp(a0.z, n0.z, invT); s += pe; P = spal[64 + lane];
        accx = fmaf(pe, P.x, accx); accy = fmaf(pe, P.y, accy);
        accz = fmaf(pe, P.z, accz); accw = fmaf(pe, P.w, accw);

        pe = gexp(a0.w, n0.w, invT); s += pe; P = spal[96 + lane];
        accx = fmaf(pe, P.x, accx); accy = fmaf(pe, P.y, accy);
        accz = fmaf(pe, P.z, accz); accw = fmaf(pe, P.w, accw);

        pe = gexp(a1.x, n1.x, invT); s += pe; P = spal[128 + lane];
        accx = fmaf(pe, P.x, accx); accy = fmaf(pe, P.y, accy);
        accz = fmaf(pe, P.z, accz); accw = fmaf(pe, P.w, accw);

        pe = gexp(a1.y, n1.y, invT); s += pe; P = spal[160 + lane];
        accx = fmaf(pe, P.x, accx); accy = fmaf(pe, P.y, accy);
        accz = fmaf(pe, P.z, accz); accw = fmaf(pe, P.w, accw);

        pe = gexp(a1.z, n1.z, invT); s += pe; P = spal[192 + lane];
        accx = fmaf(pe, P.x, accx); accy = fmaf(pe, P.y, accy);
        accz = fmaf(pe, P.z, accz); accw = fmaf(pe, P.w, accw);

        pe = gexp(a1.w, n1.w, invT); s += pe; P = spal[224 + lane];
        accx = fmaf(pe, P.x, accx); accy = fmaf(pe, P.y, accy);
        accz = fmaf(pe, P.z, accz); accw = fmaf(pe, P.w, accw);

        // 5-value butterfly reduction across the warp
#pragma unroll
        for (int off = 16; off > 0; off >>= 1) {
            s    += __shfl_xor_sync(0xffffffffu, s,    off);
            accx += __shfl_xor_sync(0xffffffffu, accx, off);
            accy += __shfl_xor_sync(0xffffffffu, accy, off);
            accz += __shfl_xor_sync(0xffffffffu, accz, off);
            accw += __shfl_xor_sync(0xffffffffu, accw, off);
        }

        if (lane == 0) {
            float inv = __fdividef(1.0f, s);
            float4 o;
            o.x = accx * inv; o.y = accy * inv; o.z = accz * inv; o.w = accw * inv;
            ((float4*)out)[(size_t)batch * hw + p] = o;
        }
    }
}

extern "C" void kernel_launch(void* const* d_in, const int* in_sizes, int n_in,
                              void* d_out, int out_size) {
    const float* images   = (const float*)d_in[0];
    const float* palettes = (const float*)d_in[1];
    const float* noise    = (const float*)d_in[2];
    const float* temp     = (const float*)d_in[3];
    float* out = (float*)d_out;

    int batches = in_sizes[1] / (KDIM * CDIM);               // 8
    int hw = (int)(in_sizes[0] / ((size_t)batches * KDIM));  // 65536

    dim3 block(256, 1, 1);
    dim3 grid(256, batches, 1); // 2048 blocks; 6/SM resident -> ~2.3 waves
    gsq_kernel<<<grid, block>>>(images, palettes, noise, temp, out, hw);
}

// round 3
// speedup vs baseline: 1.0633x; 1.0387x over previous
#include <cuda_runtime.h>
#include <cuda_bf16.h>

// Gumbel-softmax palette quantization, fused single pass.
// probs = softmax((images + gumbel)/T, axis=k);  out = einsum('bhwk,bkc->bhwc', probs, palettes)
// gumbel = -log(-log(u+EPS)+EPS)
// Single pass (no max-subtract): exp((x+g)/T) <= ~1e22 here, far from fp32 overflow.
// out_c = (sum_k p_k * pal_kc) / (sum_k p_k)
//
// R2: palette in smem (conflict-free permuted), __launch_bounds__(256,6), __ldcs streams.
// R3: persistent single-wave grid: 148 SMs x 6 blocks = 888 = 111 x 8 batches.
//     Removes wave quantization (R2 ran 2.31 waves; last wave at ~30% occ).

#define KDIM 256
#define CDIM 4
#define EPSF 1e-20f

__device__ __forceinline__ float gexp(float x, float u, float invT) {
    // w = -log(u+eps)+eps ; p = exp((x - log(w)) * invT)
    float w = EPSF - __logf(u + EPSF);
    return __expf((x - __logf(w)) * invT);
}

__global__ __launch_bounds__(256, 6)
void gsq_kernel(const float* __restrict__ images,
                const float* __restrict__ palettes,
                const float* __restrict__ noise,
                const float* __restrict__ temp,
                float* __restrict__ out,
                int hw)
{
    __shared__ float4 spal[256];   // 4KB, permuted: spal[j*32+lane] = pal[4*lane+j] (lo half), +128 hi

    const int lane = threadIdx.x & 31;
    const int wid  = threadIdx.x >> 5;
    const int batch = blockIdx.y;
    const int warps_per_block = blockDim.x >> 5;
    const int warp_global = blockIdx.x * warps_per_block + wid;
    const int warp_stride = gridDim.x * warps_per_block;   // 888 warps per batch

    const float invT = __fdividef(1.0f, temp[0]);

    // Fill smem palette, permuted so consecutive lanes hit consecutive float4s
    // (16B stride) => conflict-free LDS.128.
    {
        const float4* __restrict__ pal =
            (const float4*)(palettes + (size_t)batch * KDIM * CDIM);
        int e = threadIdx.x;                     // palette entry index 0..255
        int el = e & 127;                        // index within half
        int dst = (e & 128) + ((el & 3) << 5) + (el >> 2);
        spal[dst] = pal[e];
    }
    __syncthreads();

    const size_t base_b = (size_t)batch * hw * KDIM;

    for (int p = warp_global; p < hw; p += warp_stride) {
        const float4* __restrict__ img =
            (const float4*)(images + base_b + (size_t)p * KDIM);
        const float4* __restrict__ nse =
            (const float4*)(noise + base_b + (size_t)p * KDIM);

        // 4 independent 512B-coalesced streaming loads -> good MLP, no cache pollution
        float4 a0 = __ldcs(img + lane);
        float4 a1 = __ldcs(img + 32 + lane);
        float4 n0 = __ldcs(nse + lane);
        float4 n1 = __ldcs(nse + 32 + lane);

        float s = 0.0f;
        float accx = 0.0f, accy = 0.0f, accz = 0.0f, accw = 0.0f;

        float pe; float4 P;

        pe = gexp(a0.x, n0.x, invT); s += pe; P = spal[lane];
        accx = fmaf(pe, P.x, accx); accy = fmaf(pe, P.y, accy);
        accz = fmaf(pe, P.z, accz); accw = fmaf(pe, P.w, accw);

        pe = gexp(a0.y, n0.y, invT); s += pe; P = spal[32 + lane];
        accx = fmaf(pe, P.x, accx); accy = fmaf(pe, P.y, accy);
        accz = fmaf(pe, P.z, accz); accw = fmaf(pe, P.w, accw);

        pe = gexp(a0.z, n0.z, invT); s += pe; P = spal[64 + lane];
        accx = fmaf(pe, P.x, accx); accy = fmaf(pe, P.y, accy);
        accz = fmaf(pe, P.z, accz); accw = fmaf(pe, P.w, accw);

        pe = gexp(a0.w, n0.w, invT); s += pe; P = spal[96 + lane];
        accx = fmaf(pe, P.x, accx); accy = fmaf(pe, P.y, accy);
        accz = fmaf(pe, P.z, accz); accw = fmaf(pe, P.w, accw);

        pe = gexp(a1.x, n1.x, invT); s += pe; P = spal[128 + lane];
        accx = fmaf(pe, P.x, accx); accy = fmaf(pe, P.y, accy);
        accz = fmaf(pe, P.z, accz); accw = fmaf(pe, P.w, accw);

        pe = gexp(a1.y, n1.y, invT); s += pe; P = spal[160 + lane];
        accx = fmaf(pe, P.x, accx); accy = fmaf(pe, P.y, accy);
        accz = fmaf(pe, P.z, accz); accw = fmaf(pe, P.w, accw);

        pe = gexp(a1.z, n1.z, invT); s += pe; P = spal[192 + lane];
        accx = fmaf(pe, P.x, accx); accy = fmaf(pe, P.y, accy);
        accz = fmaf(pe, P.z, accz); accw = fmaf(pe, P.w, accw);

        pe = gexp(a1.w, n1.w, invT); s += pe; P = spal[224 + lane];
        accx = fmaf(pe, P.x, accx); accy = fmaf(pe, P.y, accy);
        accz = fmaf(pe, P.z, accz); accw = fmaf(pe, P.w, accw);

        // 5-value butterfly reduction across the warp
#pragma unroll
        for (int off = 16; off > 0; off >>= 1) {
            s    += __shfl_xor_sync(0xffffffffu, s,    off);
            accx += __shfl_xor_sync(0xffffffffu, accx, off);
            accy += __shfl_xor_sync(0xffffffffu, accy, off);
            accz += __shfl_xor_sync(0xffffffffu, accz, off);
            accw += __shfl_xor_sync(0xffffffffu, accw, off);
        }

        if (lane == 0) {
            float inv = __fdividef(1.0f, s);
            float4 o;
            o.x = accx * inv; o.y = accy * inv; o.z = accz * inv; o.w = accw * inv;
            ((float4*)out)[(size_t)batch * hw + p] = o;
        }
    }
}

extern "C" void kernel_launch(void* const* d_in, const int* in_sizes, int n_in,
                              void* d_out, int out_size) {
    const float* images   = (const float*)d_in[0];
    const float* palettes = (const float*)d_in[1];
    const float* noise    = (const float*)d_in[2];
    const float* temp     = (const float*)d_in[3];
    float* out = (float*)d_out;

    int batches = in_sizes[1] / (KDIM * CDIM);               // 8
    int hw = (int)(in_sizes[0] / ((size_t)batches * KDIM));  // 65536

    dim3 block(256, 1, 1);
    // Single full wave: 148 SMs x 6 resident blocks = 888 blocks = 111 x 8 batches.
    dim3 grid(111, batches, 1);
    gsq_kernel<<<grid, block>>>(images, palettes, noise, temp, out, hw);
}

// round 4
// speedup vs baseline: 1.0882x; 1.0234x over previous
#include <cuda_runtime.h>
#include <cuda_bf16.h>

// Gumbel-softmax palette quantization, fused single pass.
// probs = softmax((images + gumbel)/T, axis=k);  out = einsum('bhwk,bkc->bhwc', probs, palettes)
// gumbel = -log(-log(u+EPS)+EPS);  single pass (no max-subtract), out_c = (sum p*pal_c)/(sum p)
//
// R2: palette in smem (conflict-free permuted), launch_bounds(256,6), __ldcs streams.
// R3: single-wave persistent grid (888 blocks = 148x6).
// R4: instruction-diet round — f32x2 packed FMAs (PTX fma.rn.f32x2), lg2-domain gexp,
//     pointer strength reduction, packed butterfly reduction. ~265 -> ~205 instr/pixel.

#define KDIM 256
#define CDIM 4
#define EPSF 1e-20f
#define LN2F 0.69314718055994530942f
#define LOG2EF 1.44269504088896340736f

typedef unsigned long long u64;

__device__ __forceinline__ float lg2f(float x) {
    float r; asm("lg2.approx.f32 %0, %1;" : "=f"(r) : "f"(x)); return r;
}
__device__ __forceinline__ float ex2f(float x) {
    float r; asm("ex2.approx.f32 %0, %1;" : "=f"(r) : "f"(x)); return r;
}
__device__ __forceinline__ u64 pack2(float lo, float hi) {
    u64 r; asm("mov.b64 %0, {%1, %2};" : "=l"(r) : "f"(lo), "f"(hi)); return r;
}
__device__ __forceinline__ float2 unpack2(u64 v) {
    float2 r; asm("mov.b64 {%0, %1}, %2;" : "=f"(r.x), "=f"(r.y) : "l"(v)); return r;
}
__device__ __forceinline__ u64 fma2(u64 a, u64 b, u64 c) {
    u64 d; asm("fma.rn.f32x2 %0, %1, %2, %3;" : "=l"(d) : "l"(a), "l"(b), "l"(c)); return d;
}
__device__ __forceinline__ u64 add2(u64 a, u64 b) {
    u64 d; asm("add.rn.f32x2 %0, %1, %2;" : "=l"(d) : "l"(a), "l"(b)); return d;
}

// pe = exp((x - log(-log(u+eps)+eps)) * invT), computed in log2 domain:
// t1 = lg2(u+eps); w = eps - t1*ln2; t2 = lg2(w); pe = ex2(x*c1 + t2*c2)
// with c1 = invT*log2e, c2 = -invT.
__device__ __forceinline__ float gexp(float x, float u, float c1, float c2) {
    float t1 = lg2f(u + EPSF);
    float w  = fmaf(t1, -LN2F, EPSF);
    float t2 = lg2f(w);
    return ex2f(fmaf(x, c1, t2 * c2));
}

__global__ __launch_bounds__(256, 6)
void gsq_kernel(const float* __restrict__ images,
                const float* __restrict__ palettes,
                const float* __restrict__ noise,
                const float* __restrict__ temp,
                float* __restrict__ out,
                int hw)
{
    __shared__ ulonglong2 spal[256];  // 4KB; permuted: entry for (elem j, lane) at [j*32+lane]

    const int lane = threadIdx.x & 31;
    const int wid  = threadIdx.x >> 5;
    const int batch = blockIdx.y;
    const int warps_per_block = blockDim.x >> 5;
    const int warp_global = blockIdx.x * warps_per_block + wid;
    const int warp_stride = gridDim.x * warps_per_block;   // 888 warps per batch

    const float invT = __fdividef(1.0f, temp[0]);
    const float c1 = invT * LOG2EF;
    const float c2 = -invT;

    // Fill smem palette, permuted so consecutive lanes hit consecutive 16B
    // (conflict-free LDS.128). spal[(j<<5)+lane] = pal[4*lane+j] (+128 for hi half).
    {
        const float4* __restrict__ pal =
            (const float4*)(palettes + (size_t)batch * KDIM * CDIM);
        int e = threadIdx.x;
        int el = e & 127;
        int dst = (e & 128) + ((el & 3) << 5) + (el >> 2);
        ((float4*)spal)[dst] = pal[e];
    }
    __syncthreads();

    const size_t base_b = (size_t)batch * hw * KDIM;
    const float4* img = (const float4*)(images + base_b) + (size_t)warp_global * 64 + lane;
    const float4* nse = (const float4*)(noise  + base_b) + (size_t)warp_global * 64 + lane;
    float4*       outp = (float4*)out + (size_t)batch * hw + warp_global;
    const size_t  step = (size_t)warp_stride * 64;

    for (int p = warp_global; p < hw; p += warp_stride,
                                       img += step, nse += step, outp += warp_stride) {
        // 4 independent 512B-coalesced streaming loads (MLP=4), no cache pollution
        float4 a0 = __ldcs(img);
        float4 a1 = __ldcs(img + 32);
        float4 n0 = __ldcs(nse);
        float4 n1 = __ldcs(nse + 32);

        u64 accA = 0, accB = 0, s2 = 0;   // packed (x,y), (z,w), (s_even,s_odd)
        float pe0, pe1; u64 d; ulonglong2 P;

        pe0 = gexp(a0.x, n0.x, c1, c2);
        pe1 = gexp(a0.y, n0.y, c1, c2);
        s2 = add2(s2, pack2(pe0, pe1));
        P = spal[lane];       d = pack2(pe0, pe0);
        accA = fma2(d, P.x, accA); accB = fma2(d, P.y, accB);
        P = spal[32 + lane];  d = pack2(pe1, pe1);
        accA = fma2(d, P.x, accA); accB = fma2(d, P.y, accB);

        pe0 = gexp(a0.z, n0.z, c1, c2);
        pe1 = gexp(a0.w, n0.w, c1, c2);
        s2 = add2(s2, pack2(pe0, pe1));
        P = spal[64 + lane];  d = pack2(pe0, pe0);
        accA = fma2(d, P.x, accA); accB = fma2(d, P.y, accB);
        P = spal[96 + lane];  d = pack2(pe1, pe1);
        accA = fma2(d, P.x, accA); accB = fma2(d, P.y, accB);

        pe0 = gexp(a1.x, n1.x, c1, c2);
        pe1 = gexp(a1.y, n1.y, c1, c2);
        s2 = add2(s2, pack2(pe0, pe1));
        P = spal[128 + lane]; d = pack2(pe0, pe0);
        accA = fma2(d, P.x, accA); accB = fma2(d, P.y, accB);
        P = spal[160 + lane]; d = pack2(pe1, pe1);
        accA = fma2(d, P.x, accA); accB = fma2(d, P.y, accB);

        pe0 = gexp(a1.z, n1.z, c1, c2);
        pe1 = gexp(a1.w, n1.w, c1, c2);
        s2 = add2(s2, pack2(pe0, pe1));
        P = spal[192 + lane]; d = pack2(pe0, pe0);
        accA = fma2(d, P.x, accA); accB = fma2(d, P.y, accB);
        P = spal[224 + lane]; d = pack2(pe1, pe1);
        accA = fma2(d, P.x, accA); accB = fma2(d, P.y, accB);

        // Butterfly reduction: s scalar + two packed pairs (5 SHFL + 2 ADD2 + 1 FADD per stage)
        float2 sp = unpack2(s2);
        float s = sp.x + sp.y;
#pragma unroll
        for (int off = 16; off > 0; off >>= 1) {
            s += __shfl_xor_sync(0xffffffffu, s, off);
            float2 ua = unpack2(accA);
            float2 ub = unpack2(accB);
            accA = add2(accA, pack2(__shfl_xor_sync(0xffffffffu, ua.x, off),
                                    __shfl_xor_sync(0xffffffffu, ua.y, off)));
            accB = add2(accB, pack2(__shfl_xor_sync(0xffffffffu, ub.x, off),
                                    __shfl_xor_sync(0xffffffffu, ub.y, off)));
        }

        if (lane == 0) {
            float inv = __fdividef(1.0f, s);
            float2 oa = unpack2(accA);
            float2 ob = unpack2(accB);
            float4 o;
            o.x = oa.x * inv; o.y = oa.y * inv;
            o.z = ob.x * inv; o.w = ob.y * inv;
            *outp = o;
        }
    }
}

extern "C" void kernel_launch(void* const* d_in, const int* in_sizes, int n_in,
                              void* d_out, int out_size) {
    const float* images   = (const float*)d_in[0];
    const float* palettes = (const float*)d_in[1];
    const float* noise    = (const float*)d_in[2];
    const float* temp     = (const float*)d_in[3];
    float* out = (float*)d_out;

    int batches = in_sizes[1] / (KDIM * CDIM);               // 8
    int hw = (int)(in_sizes[0] / ((size_t)batches * KDIM));  // 65536

    dim3 block(256, 1, 1);
    // Single full wave: 148 SMs x 6 resident blocks = 888 blocks = 111 x 8 batches.
    dim3 grid(111, batches, 1);
    gsq_kernel<<<grid, block>>>(images, palettes, noise, temp, out, hw);
}